// round 4
// baseline (speedup 1.0000x reference)
#include <cuda_runtime.h>
#include <cstdint>

#define N_NODES 12288
#define H_DIM   128
#define E_EDGES 393216
#define NEGVAL  (-1000000000.0f)
#define ROW4    (N_NODES / 4)      // 3072 float4 per row

// Static scratch (no cudaMalloc allowed).
__device__ float g_d1[N_NODES];
__device__ float g_d2[N_NODES];
__device__ int   g_counts[N_NODES];
__device__ int   g_cursor[N_NODES];
__device__ int   g_base[N_NODES + 1];
__device__ int2  g_edge[E_EDGES];        // (src_col, float_as_int(val))

// ---------------------------------------------------------------------------
// Z: zero histogram counters.
// ---------------------------------------------------------------------------
__global__ void zero_kernel() {
    int i = blockIdx.x * blockDim.x + threadIdx.x;
    if (i < N_NODES) g_counts[i] = 0;
}

// ---------------------------------------------------------------------------
// A: per-node dots (1 warp/node) + per-edge histogram (1 thread/edge).
//    Grid is exactly E threads = N*32 threads.
// ---------------------------------------------------------------------------
__global__ void dots_hist_kernel(const float* __restrict__ h,
                                 const float* __restrict__ W,
                                 const int*   __restrict__ dests) {
    int t    = (int)(blockIdx.x * blockDim.x + threadIdx.x);
    int gw   = t >> 5;
    int lane = t & 31;

    // dots
    if (gw < N_NODES) {
        const float4* hr4 = (const float4*)(h + (size_t)gw * H_DIM);
        const float4* w14 = (const float4*)(W);
        const float4* w24 = (const float4*)(W + H_DIM);
        float4 hv = __ldg(&hr4[lane]);
        float4 w1 = __ldg(&w14[lane]);
        float4 w2 = __ldg(&w24[lane]);
        float s1 = fmaf(hv.x, w1.x, fmaf(hv.y, w1.y, fmaf(hv.z, w1.z, hv.w * w1.w)));
        float s2 = fmaf(hv.x, w2.x, fmaf(hv.y, w2.y, fmaf(hv.z, w2.z, hv.w * w2.w)));
#pragma unroll
        for (int off = 16; off; off >>= 1) {
            s1 += __shfl_down_sync(0xffffffffu, s1, off);
            s2 += __shfl_down_sync(0xffffffffu, s2, off);
        }
        if (lane == 0) { g_d1[gw] = s1; g_d2[gw] = s2; }
    }

    // histogram over dest rows
    if (t < E_EDGES) {
        atomicAdd(&g_counts[dests[t]], 1);
    }
}

// ---------------------------------------------------------------------------
// B: single-block exclusive scan of counts -> base; zero cursors.
//    1024 threads x 12 elements each = 12288.
// ---------------------------------------------------------------------------
__global__ __launch_bounds__(1024) void scan_kernel() {
    __shared__ int tsum[1024];
    int t = threadIdx.x;

    int local[12];
    int s = 0;
#pragma unroll
    for (int i = 0; i < 12; i++) {
        local[i] = s;
        s += g_counts[t * 12 + i];
    }
    tsum[t] = s;
    __syncthreads();

    // Hillis-Steele inclusive scan over per-thread sums
    for (int off = 1; off < 1024; off <<= 1) {
        int v = (t >= off) ? tsum[t - off] : 0;
        __syncthreads();
        tsum[t] += v;
        __syncthreads();
    }

    int tbase = (t == 0) ? 0 : tsum[t - 1];
#pragma unroll
    for (int i = 0; i < 12; i++) {
        g_base[t * 12 + i]   = tbase + local[i];
        g_cursor[t * 12 + i] = 0;
    }
    if (t == 1023) g_base[N_NODES] = tsum[1023];
}

// ---------------------------------------------------------------------------
// C: compute edge values and place into per-row buckets.
// ---------------------------------------------------------------------------
__global__ void place_kernel(const int*   __restrict__ src,
                             const int*   __restrict__ dst,
                             const float* __restrict__ wts,
                             const float* __restrict__ W,
                             const float* __restrict__ b) {
    int e = (int)(blockIdx.x * blockDim.x + threadIdx.x);
    if (e >= E_EDGES) return;
    int s = src[e];
    int d = dst[e];
    float val = g_d1[d] + g_d2[s]
              + fmaf(wts[e], __ldg(&W[2 * H_DIM]), __ldg(&b[0]));
    int pos = g_base[d] + atomicAdd(&g_cursor[d], 1);
    g_edge[pos] = make_int2(s, __float_as_int(val));
}

// ---------------------------------------------------------------------------
// D: fill + merge. Build each 48KB row in static smem (NEG + edges), then
//    stream it out. DRAM sees only the sequential 604MB write stream —
//    no random-row activations.
// ---------------------------------------------------------------------------
__global__ __launch_bounds__(512) void fill_merge_kernel(float4* __restrict__ out) {
    __shared__ float row[N_NODES];               // exactly 48 KB
    float4* row4 = (float4*)row;
    const float4 v = make_float4(NEGVAL, NEGVAL, NEGVAL, NEGVAL);

    for (int r = blockIdx.x; r < N_NODES; r += gridDim.x) {
#pragma unroll
        for (int i = threadIdx.x; i < ROW4; i += 512) row4[i] = v;
        __syncthreads();

        int beg = g_base[r];
        int end = g_base[r + 1];
        for (int i = beg + (int)threadIdx.x; i < end; i += 512) {
            int2 ev = g_edge[i];
            row[ev.x] = __int_as_float(ev.y);    // dup races benign
        }
        __syncthreads();

        float4* dstp = out + (size_t)r * ROW4;
#pragma unroll
        for (int i = threadIdx.x; i < ROW4; i += 512) __stcs(&dstp[i], row4[i]);
        __syncthreads();                          // before smem reuse
    }
}

// ---------------------------------------------------------------------------
// Launch. Input order (metadata): h, sources, dests, weights, W, b
// ---------------------------------------------------------------------------
extern "C" void kernel_launch(void* const* d_in, const int* in_sizes, int n_in,
                              void* d_out, int out_size) {
    const float* h       = (const float*)d_in[0];
    const int*   sources = (const int*)  d_in[1];
    const int*   dests   = (const int*)  d_in[2];
    const float* weights = (const float*)d_in[3];
    const float* W       = (const float*)d_in[4];
    const float* b       = (const float*)d_in[5];
    float*       out     = (float*)d_out;

    zero_kernel<<<(N_NODES + 255) / 256, 256>>>();

    dots_hist_kernel<<<E_EDGES / 256, 256>>>(h, W, dests);   // 1536 blocks

    scan_kernel<<<1, 1024>>>();

    place_kernel<<<E_EDGES / 256, 256>>>(sources, dests, weights, W, b);

    fill_merge_kernel<<<148 * 4, 512>>>((float4*)out);       // 4 blocks/SM, 1 wave
}